// round 14
// baseline (speedup 1.0000x reference)
#include <cuda_runtime.h>

// Shapes (fixed)
#define Bn 16
#define In 32
#define Cn 8
#define Jn 10
#define Dn 16
#define Xn 576    // D*H*W (one CTA owns a full (b,j) slice)
#define NT 288    // threads; each owns x and x+288
#define HWn 36
#define EPSf 1e-7f
#define GRID2 (Bn*Jn)   // 160 CTAs, 2/SM co-resident (113-reg budget)
#define JX (Jn*Xn)      // 5760

// Cross-CTA comm scratch, parity double-buffered (WAR-safe with one grid
// barrier per iteration; validated in R9).
__device__ float    g_nPart[2][GRID2];
__device__ float    g_aPart[2][GRID2 * In];   // [entry][i], 128B coalesced rows
__device__ unsigned g_cnt;
__device__ unsigned g_gen;

__device__ __forceinline__ float squash_k(float n) {
    float n2 = n * n;
    return (n2 / (1.f + n2)) / (n + EPSf);
}

__device__ __forceinline__ void gridBarrier() {
    __threadfence();
    __syncthreads();
    if (threadIdx.x == 0) {
        unsigned g0 = *(volatile unsigned*)&g_gen;
        unsigned a = atomicAdd(&g_cnt, 1u);
        if (a == GRID2 - 1) {
            atomicExch(&g_cnt, 0u);
            __threadfence();
            atomicAdd(&g_gen, 1u);
        } else {
            while (*(volatile unsigned*)&g_gen == g0) { }
        }
        __threadfence();
    }
    __syncthreads();
}

// Block sum over 288 threads (9 warps); valid on thread 0.
__device__ __forceinline__ float blockReduceSum288(float v) {
    __shared__ float red[9];
    int lane = threadIdx.x & 31, w = threadIdx.x >> 5;
    #pragma unroll
    for (int o = 16; o > 0; o >>= 1) v += __shfl_down_sync(0xffffffffu, v, o);
    if (lane == 0) red[w] = v;
    __syncthreads();
    float s = 0.f;
    if (threadIdx.x == 0) {
        #pragma unroll
        for (int k = 0; k < 9; k++) s += red[k];
    }
    return s;
}

__global__ void __launch_bounds__(NT, 2) routing_all(
    const float* __restrict__ u, const float* __restrict__ bias,
    float* __restrict__ out)
{
    // dynamic smem: U tile (32x576 = 73,728B) + 3-deep staging ring (3x9216B)
    extern __shared__ __align__(16) float dyn[];
    float* Us  = dyn;                 // Us[i*Xn + x]
    float* stg = dyn + In * Xn;       // 3 buffers x 4 rows x 576 floats
    __shared__ float ss[Xn];
    __shared__ float sb[In * Jn];
    __shared__ float cs[In];
    __shared__ float kb_sh[Bn];
    int bj = blockIdx.x;
    int b = bj / Jn, j = bj % Jn;
    int x = threadIdx.x;
    int w = x >> 5, lane = x & 31;
    float bias0 = bias[j * Dn + x / HWn];
    float bias1 = bias[j * Dn + (x + NT) / HWn];

    for (int t = x; t < In * Jn; t += NT) sb[t] = 0.f;

    // ---- Load phase: cp.async pipelined c-reduction. 94 MB streamed once.
    // substep s: i = s>>1, rows c = 4*(s&1)..+3 staged into ring slot s%3.
    // In-flight = 3 x 9.2KB per CTA, independent of register budget.
    const float* ubase = u + (size_t)b * In * Cn * JX + (size_t)j * Xn;
    unsigned stgB = (unsigned)__cvta_generic_to_shared(stg);
    // per-thread chunk coords (576 16B-chunks per substep; this thread: x, x+288)
    int r0 = x / 144,        c0 = (x % 144) * 4;
    int r1 = (x + NT) / 144, c1 = ((x + NT) % 144) * 4;

    #define ISSUE(s_) do {                                                   \
        int i_ = (s_) >> 1, h_ = (s_) & 1;                                   \
        const float* rb = ubase + ((size_t)i_ * Cn + 4 * h_) * JX;           \
        unsigned db = stgB + (unsigned)((s_) % 3) * 9216u;                   \
        asm volatile("cp.async.cg.shared.global [%0], [%1], 16;\n"           \
            :: "r"(db + (unsigned)(r0 * Xn + c0) * 4u),                      \
               "l"(rb + (size_t)r0 * JX + c0) : "memory");                   \
        asm volatile("cp.async.cg.shared.global [%0], [%1], 16;\n"           \
            :: "r"(db + (unsigned)(r1 * Xn + c1) * 4u),                      \
               "l"(rb + (size_t)r1 * JX + c1) : "memory");                   \
        asm volatile("cp.async.commit_group;\n" ::: "memory");               \
    } while (0)

    ISSUE(0); ISSUE(1); ISSUE(2);

    float acc0 = 0.f, acc1 = 0.f, tot0 = 0.f, tot1 = 0.f;
    #pragma unroll 1
    for (int s = 0; s < In * 2; s++) {
        int i = s >> 1, h = s & 1;
        // DRAIN FIX: after the last issue (s_=63 at s=60), the pending-group
        // count shrinks; wait_group 2 no longer guarantees group s completed.
        if (s <= In * 2 - 3)
            asm volatile("cp.async.wait_group 2;\n" ::: "memory");
        else if (s == In * 2 - 2)
            asm volatile("cp.async.wait_group 1;\n" ::: "memory");
        else
            asm volatile("cp.async.wait_group 0;\n" ::: "memory");
        __syncthreads();                    // all threads' copies of slot s%3 visible
        const float* bf = stg + (s % 3) * (4 * Xn);
        if (h == 0) { acc0 = 0.f; acc1 = 0.f; }
        #pragma unroll
        for (int r = 0; r < 4; r++) {
            acc0 += bf[r * Xn + x];
            acc1 += bf[r * Xn + x + NT];
        }
        __syncthreads();                    // everyone done reading slot s%3
        if (s + 3 < In * 2) ISSUE(s + 3);   // refill slot (s+3)%3 == s%3
        if (h == 1) {
            Us[i * Xn + x]      = acc0;
            Us[i * Xn + x + NT] = acc1;
            tot0 += acc0;
            tot1 += acc1;
        }
    }
    #undef ISSUE
    __syncthreads();

    float s0 = 0.f, s1 = 0.f;
    #pragma unroll 1
    for (int iter = 0; iter < 3; iter++) {
        int pb = iter & 1;

        // ---- routing update (iter > 0), coalesced: lane = i, 128B rows.
        if (iter > 0) {
            int prev = (iter - 1) & 1;
            if (x < Bn) {
                float nn = 0.f;
                #pragma unroll
                for (int t = 0; t < Jn; t++) nn += __ldcg(&g_nPart[prev][x * Jn + t]);
                kb_sh[x] = squash_k(nn);
            }
            __syncthreads();
            for (int jj = w; jj < Jn; jj += 9) {
                float a = 0.f;
                #pragma unroll
                for (int bb = 0; bb < Bn; bb++) {
                    int ent = bb * Jn + jj;
                    a += kb_sh[bb] * __ldcg(&g_aPart[prev][(size_t)ent * In + lane]);
                }
                sb[lane * Jn + jj] += a;
            }
            __syncthreads();
            if (x < In) {
                float mx = -1e30f;
                #pragma unroll
                for (int jj = 0; jj < Jn; jj++) mx = fmaxf(mx, sb[x * Jn + jj]);
                float den = 0.f;
                #pragma unroll
                for (int jj = 0; jj < Jn; jj++) den += expf(sb[x * Jn + jj] - mx);
                cs[x] = expf(sb[x * Jn + j] - mx) / den;
            }
            __syncthreads();
        }

        // ---- s_j: thread owns x and x+288
        if (iter == 0) {
            s0 = tot0 * (1.0f / Jn) + bias0;   // Σi accumulated during load
            s1 = tot1 * (1.0f / Jn) + bias1;
        } else {
            float a0 = 0.f, a1 = 0.f;
            #pragma unroll
            for (int i = 0; i < In; i++) {
                float c = cs[i];
                a0 += c * Us[i * Xn + x];
                a1 += c * Us[i * Xn + x + NT];
            }
            s0 = a0 + bias0;
            s1 = a1 + bias1;
        }
        float n = blockReduceSum288(fabsf(s0) + fabsf(s1));
        if (x == 0) g_nPart[pb][bj] = n;

        if (iter == 2) break;                  // final agreement is dead

        ss[x] = s0;
        ss[x + NT] = s1;
        __syncthreads();
        if (w < 8) {
            #pragma unroll
            for (int ii = 0; ii < 4; ii++) {
                int i = w * 4 + ii;
                float a = 0.f;
                #pragma unroll
                for (int xx = lane; xx < Xn; xx += 32) a += Us[i * Xn + xx] * ss[xx];
                #pragma unroll
                for (int o = 16; o > 0; o >>= 1) a += __shfl_down_sync(0xffffffffu, a, o);
                if (lane == 0) g_aPart[pb][(size_t)bj * In + i] = a;
            }
        }
        gridBarrier();
    }

    // ---- final squash (iter-2 norms in buffer 0)
    gridBarrier();
    if (x == 0) {
        float nn = 0.f;
        #pragma unroll
        for (int t = 0; t < Jn; t++) nn += __ldcg(&g_nPart[0][b * Jn + t]);
        kb_sh[0] = squash_k(nn);
    }
    __syncthreads();
    float kb = kb_sh[0];
    out[(size_t)bj * Xn + x]      = kb * s0;
    out[(size_t)bj * Xn + x + NT] = kb * s1;
}

extern "C" void kernel_launch(void* const* d_in, const int* in_sizes, int n_in,
                              void* d_out, int out_size) {
    const float* u    = (const float*)d_in[0];
    const float* bias = (const float*)d_in[1];
    float* out = (float*)d_out;
    const int dyn_smem = (In * Xn + 3 * 4 * Xn) * sizeof(float);  // 101,376 B
    cudaFuncSetAttribute(routing_all,
                         cudaFuncAttributeMaxDynamicSharedMemorySize, dyn_smem);
    routing_all<<<GRID2, NT, dyn_smem>>>(u, bias, out);
}